// round 16
// baseline (speedup 1.0000x reference)
#include <cuda_runtime.h>
#include <cuda_fp16.h>
#include <cstdint>

// Problem constants (fixed: B=8, T=2048, D=2048)
#define B_SZ 8
#define T_SZ 2048
#define D_SZ 2048
#define M_SZ (B_SZ * T_SZ)        // 16384
#define CH_SZ (B_SZ * D_SZ)       // 16384 channels
#define CH2 (CH_SZ / 2)           // 8192 channel-pairs
#define SEG_LEN 64
#define N_SEG (T_SZ / SEG_LEN)    // 32

// ---------------- device scratch (static: no runtime allocation) ------------
__device__ __half g_xh[(size_t)M_SZ * D_SZ];     // fp16(x)
__device__ __half g_wh[(size_t)3 * D_SZ * D_SZ]; // fp16(W) for Wk,Wv,Wr
__device__ __half g_kh[(size_t)M_SZ * D_SZ];     // k (fp16)
__device__ __half g_vh[(size_t)M_SZ * D_SZ];     // v (fp16)
__device__ __half g_rh[(size_t)M_SZ * D_SZ];     // r (fp16)
__device__ float2 g_cn[(size_t)N_SEG * CH2];     // per-seg carry numerator (2ch)
__device__ float2 g_cd[(size_t)N_SEG * CH2];     // per-seg carry denominator

// ---------------- helpers -----------------------------------------------------
__device__ __forceinline__ uint32_t smem_u32(const void* p) {
    uint32_t a;
    asm("{ .reg .u64 t; cvta.to.shared.u64 t, %1; cvt.u32.u64 %0, t; }" : "=r"(a) : "l"(p));
    return a;
}
__device__ __forceinline__ void cp16(uint32_t dst, const void* src) {
    asm volatile("cp.async.cg.shared.global [%0], [%1], 16;" :: "r"(dst), "l"(src));
}
__device__ __forceinline__ void cp16z(uint32_t dst, const void* src, uint32_t src_sz) {
    asm volatile("cp.async.cg.shared.global [%0], [%1], 16, %2;"
                 :: "r"(dst), "l"(src), "r"(src_sz));
}
#define SWZ128(o) ((o) ^ (((o) >> 3) & 0x70))

__device__ __forceinline__ void ldsm_x4(uint32_t* r, uint32_t addr) {
    asm volatile("ldmatrix.sync.aligned.m8n8.x4.shared.b16 {%0,%1,%2,%3}, [%4];"
                 : "=r"(r[0]), "=r"(r[1]), "=r"(r[2]), "=r"(r[3]) : "r"(addr));
}
__device__ __forceinline__ void mma16816(float* c, const uint32_t* a, const uint32_t* b) {
    asm volatile(
        "mma.sync.aligned.m16n8k16.row.col.f32.f16.f16.f32 "
        "{%0,%1,%2,%3}, {%4,%5,%6,%7}, {%8,%9}, {%0,%1,%2,%3};"
        : "+f"(c[0]), "+f"(c[1]), "+f"(c[2]), "+f"(c[3])
        : "r"(a[0]), "r"(a[1]), "r"(a[2]), "r"(a[3]), "r"(b[0]), "r"(b[1]));
}

__device__ __forceinline__ void cvt8(const float* __restrict__ src, __half* __restrict__ dst,
                                     size_t i) {
    float4 v0 = *(const float4*)(src + i);
    float4 v1 = *(const float4*)(src + i + 4);
    __half2* op = (__half2*)(dst + i);
    op[0] = __halves2half2(__float2half_rn(v0.x), __float2half_rn(v0.y));
    op[1] = __halves2half2(__float2half_rn(v0.z), __float2half_rn(v0.w));
    op[2] = __halves2half2(__float2half_rn(v1.x), __float2half_rn(v1.y));
    op[3] = __halves2half2(__float2half_rn(v1.z), __float2half_rn(v1.w));
}

// ---------------- launch 1 conversion: x, Wk, Wv only ---------------------------
#define X_OCT ((size_t)M_SZ * D_SZ / 8)          // 4194304
#define W1_OCT ((size_t)2 * D_SZ * D_SZ / 8)     // 1048576 (Wk + Wv)
#define CV1_TOTAL (X_OCT + W1_OCT)

__global__ void convert_xkv_kernel(const float* __restrict__ x,
                                   const float* __restrict__ Wk,
                                   const float* __restrict__ Wv) {
    size_t q = (size_t)blockIdx.x * blockDim.x + threadIdx.x;
    if (q >= CV1_TOTAL) return;
    const float* src;
    __half* dst;
    size_t i;
    if (q < X_OCT) {
        i = q * 8;
        src = x;
        dst = g_xh;
    } else {
        size_t wq = q - X_OCT;
        const size_t wsz = (size_t)D_SZ * D_SZ;
        size_t z = wq / (wsz / 8);          // 0 or 1
        i = (wq - z * (wsz / 8)) * 8;
        src = (z == 0) ? Wk : Wv;
        dst = g_wh + z * wsz;
    }
    cvt8(src, dst, i);
}

// ---------------- GEMM device body (frozen config from R8/R11) -----------------
#define BM 128
#define BN 128
#define BK 64
#define N_CHUNK (D_SZ / BK)        // 32
#define TILE_B 16384
#define STAGE_BYTES (2 * TILE_B)
#define N_STAGE 3
#define GEMM_SMEM (N_STAGE * STAGE_BYTES)   // 96 KB
#define N_GEMM_XY ((D_SZ / BN) * (M_SZ / BM))   // 2048 tiles per z

__device__ __forceinline__ void gemm_tile_body(int z, int bx, int by, char* smem) {
    const uint32_t sbase = smem_u32(smem);
    const int tid = threadIdx.x;
    const int wid = tid >> 5;
    const int lane = tid & 31;
    const int wm = wid & 1;
    const int wn = wid >> 1;

    const int m0 = by * BM;
    const int n0 = bx * BN;
    const bool shift = (z < 2);

    const __half* B_h = g_wh + (size_t)z * D_SZ * D_SZ;
    __half* Ch = (z == 0) ? g_kh : (z == 1) ? g_vh : g_rh;

    float acc[4][4][4];
#pragma unroll
    for (int i = 0; i < 4; i++)
#pragma unroll
        for (int j = 0; j < 4; j++)
#pragma unroll
            for (int q = 0; q < 4; q++) acc[i][j][q] = 0.f;

    auto load_stage = [&](int c, int s) {
        const int kt = c * BK;
        const uint32_t st = sbase + s * STAGE_BYTES;
#pragma unroll
        for (int it = 0; it < 4; it++) {
            const int i = tid + it * 256;
            const int row = i >> 3, seg = i & 7;
            const uint32_t sw = SWZ128((uint32_t)(row * 128 + seg * 16));
            const int rm = m0 + row;
            uint32_t sz = 16;
            int srow = rm;
            if (shift) {
                if ((rm & (T_SZ - 1)) == 0) sz = 0;
                else srow = rm - 1;
            }
            cp16z(st + sw, g_xh + (size_t)srow * D_SZ + kt + seg * 8, sz);
            cp16(st + TILE_B + sw, B_h + (size_t)(n0 + row) * D_SZ + kt + seg * 8);
        }
        asm volatile("cp.async.commit_group;" ::: "memory");
    };

    load_stage(0, 0);
    load_stage(1, 1);
    load_stage(2, 2);

    const int a_row = lane & 15;
    const int a_half = lane >> 4;
    const int b_nr = (lane & 7) + ((lane >> 4) << 3);
    const int b_half = (lane >> 3) & 1;

    int s = 0;
    int fs = 2;
    for (int c = 0; c < N_CHUNK; c++) {
        if (c == 0)                 asm volatile("cp.async.wait_group 2;" ::: "memory");
        else if (c == N_CHUNK - 1)  asm volatile("cp.async.wait_group 0;" ::: "memory");
        else                        asm volatile("cp.async.wait_group 1;" ::: "memory");
        __syncthreads();

        if (c >= 1 && c + 2 < N_CHUNK) load_stage(c + 2, fs);

        const uint32_t sA = sbase + s * STAGE_BYTES;
        const uint32_t sB = sA + TILE_B;

#pragma unroll
        for (int ks = 0; ks < 4; ks++) {
            uint32_t aa[4][4], bb[2][4];
#pragma unroll
            for (int mi = 0; mi < 4; mi++) {
                const uint32_t off = SWZ128(
                    (uint32_t)((wm * 64 + mi * 16 + a_row) * 128 + ks * 32 + a_half * 16));
                ldsm_x4(aa[mi], sA + off);
            }
#pragma unroll
            for (int j = 0; j < 2; j++) {
                const uint32_t off = SWZ128(
                    (uint32_t)((wn * 32 + j * 16 + b_nr) * 128 + ks * 32 + b_half * 16));
                ldsm_x4(bb[j], sB + off);
            }
#pragma unroll
            for (int mi = 0; mi < 4; mi++)
#pragma unroll
                for (int ni = 0; ni < 4; ni++)
                    mma16816(acc[mi][ni], aa[mi], &bb[ni >> 1][(ni & 1) * 2]);
        }
        fs = s;
        s = (s == N_STAGE - 1) ? 0 : s + 1;
    }

#pragma unroll
    for (int mi = 0; mi < 4; mi++) {
        const int gm = m0 + wm * 64 + mi * 16 + (lane >> 2);
#pragma unroll
        for (int ni = 0; ni < 4; ni++) {
            const int gn = n0 + wn * 32 + ni * 8 + (lane & 3) * 2;
            __half* p0 = Ch + (size_t)gm * D_SZ + gn;
            __half* p1 = p0 + 8 * D_SZ;
            *(__half2*)p0 = __halves2half2(__float2half_rn(acc[mi][ni][0]),
                                           __float2half_rn(acc[mi][ni][1]));
            *(__half2*)p1 = __halves2half2(__float2half_rn(acc[mi][ni][2]),
                                           __float2half_rn(acc[mi][ni][3]));
        }
    }
}

// ---------------- p1 device body (2 channels/thread) ---------------------------
__device__ __forceinline__ void wkv_p1_body(int gid, const float* __restrict__ time_decay) {
    const int c2 = gid & (CH2 - 1);
    const int seg = gid >> 13;
    const int c = c2 * 2;
    const int d = c & (D_SZ - 1);
    const int b = c >> 11;

    const float2 tdv = *(const float2*)(time_decay + d);
    const float wx = __expf(-__expf(tdv.x));
    const float wy = __expf(-__expf(tdv.y));

    const size_t base = (size_t)b * T_SZ * D_SZ + (size_t)seg * SEG_LEN * D_SZ + d;
    const __half2* kp = (const __half2*)(g_kh + base);
    const __half2* vp = (const __half2*)(g_vh + base);

    float nx = 0.f, ny = 0.f, dx = 0.f, dy = 0.f;
    for (int t = 0; t < SEG_LEN; t += 8) {
        float2 kk[8], vv[8];
#pragma unroll
        for (int i = 0; i < 8; i++) {
            const size_t o = (size_t)(t + i) * (D_SZ / 2);
            kk[i] = __half22float2(kp[o]);
            vv[i] = __half22float2(vp[o]);
        }
#pragma unroll
        for (int i = 0; i < 8; i++) {
            const float ekx = __expf(kk[i].x);
            const float eky = __expf(kk[i].y);
            nx = fmaf(wx, nx, ekx * vv[i].x);
            ny = fmaf(wy, ny, eky * vv[i].y);
            dx = fmaf(wx, dx, ekx);
            dy = fmaf(wy, dy, eky);
        }
    }
    g_cn[gid] = make_float2(nx, ny);
    g_cd[gid] = make_float2(dx, dy);
}

// ---------------- kernel 2: k,v GEMMs + interleaved Wr conversion ---------------
// Flat grid: 4096 GEMM tiles (z=0,1) + 512 Wr-conversion blocks (32 elems/thr).
// Every 9th block is a conversion block so the tiny conversion hides inside
// the GEMM waves; kv GEMM doesn't need Wr, the later r-GEMM launch does.
#define WR_CONV_BLKS 512                      // D*D / (32*256)
#define KV_BLKS (2 * N_GEMM_XY)               // 4096
#define KV_MERGE_BLKS (KV_BLKS + WR_CONV_BLKS)  // 4608

__global__ __launch_bounds__(256, 2)
void gemm_kv_wr_kernel(const float* __restrict__ Wr) {
    extern __shared__ char smem[];
    const int b = blockIdx.x;
    if ((b % 9) == 8) {
        // Wr conversion block: 256 threads x 32 elems = 8192 elems
        const size_t base = (size_t)(b / 9) * 8192 + (size_t)threadIdx.x * 32;
        __half* dst = g_wh + (size_t)2 * D_SZ * D_SZ;
#pragma unroll
        for (int j = 0; j < 4; j++) cvt8(Wr, dst, base + j * 8);
    } else {
        const int gemm_idx = (b / 9) * 8 + (b % 9);   // 0..4095
        const int z = gemm_idx >> 11;                  // 0 or 1
        const int xy = gemm_idx & (N_GEMM_XY - 1);
        gemm_tile_body(z, xy & ((D_SZ / BN) - 1), xy >> 4, smem);
    }
}

// ---------------- kernel 3: r GEMM interleaved with p1 --------------------------
#define N_P1_BLK ((N_SEG - 1) * CH2 / 256)        // 992
#define MERGE_BLKS (N_GEMM_XY + N_P1_BLK)         // 3040
#define INTERLEAVE_END (3 * N_P1_BLK)             // 2976

__global__ __launch_bounds__(256, 2)
void gemm_r_p1_kernel(const float* __restrict__ time_decay) {
    extern __shared__ char smem[];
    const int b = blockIdx.x;
    int gemm_idx = -1;
    int p1_blk = -1;
    if (b < INTERLEAVE_END) {
        if ((b % 3) == 2) p1_blk = b / 3;
        else              gemm_idx = (b / 3) * 2 + (b % 3);
    } else {
        gemm_idx = 2 * N_P1_BLK + (b - INTERLEAVE_END);
    }

    if (p1_blk >= 0) {
        wkv_p1_body(p1_blk * 256 + threadIdx.x, time_decay);
    } else {
        const int bx = gemm_idx & ((D_SZ / BN) - 1);
        const int by = gemm_idx >> 4;
        gemm_tile_body(2, bx, by, smem);
    }
}

// ---------------- p2: final scan + output --------------------------------------
__global__ void wkv_p2_kernel(const float* __restrict__ time_decay,
                              const float* __restrict__ x,
                              float* __restrict__ out) {
    const int gid = blockIdx.x * blockDim.x + threadIdx.x;  // < N_SEG*CH2
    const int c2 = gid & (CH2 - 1);
    const int seg = gid >> 13;
    const int c = c2 * 2;
    const int d = c & (D_SZ - 1);
    const int b = c >> 11;

    const float2 tdv = *(const float2*)(time_decay + d);
    const float ex = __expf(tdv.x), ey = __expf(tdv.y);
    const float wx = __expf(-ex), wy = __expf(-ey);
    const float wlx = __expf(-(float)SEG_LEN * ex);
    const float wly = __expf(-(float)SEG_LEN * ey);

    float nx = 0.f, ny = 0.f, dx = 0.f, dy = 0.f;
    for (int i = 0; i < seg; i++) {
        const float2 cn = g_cn[i * CH2 + c2];
        const float2 cd = g_cd[i * CH2 + c2];
        nx = fmaf(wlx, nx, cn.x);
        ny = fmaf(wly, ny, cn.y);
        dx = fmaf(wlx, dx, cd.x);
        dy = fmaf(wly, dy, cd.y);
    }

    const size_t base = (size_t)b * T_SZ * D_SZ + (size_t)seg * SEG_LEN * D_SZ + d;
    const __half2* kp = (const __half2*)(g_kh + base);
    const __half2* vp = (const __half2*)(g_vh + base);
    const __half2* rp = (const __half2*)(g_rh + base);
    float* op = out + base;

    for (int t = 0; t < SEG_LEN; t += 8) {
        float2 kk[8], vv[8], rr[8];
#pragma unroll
        for (int i = 0; i < 8; i++) {
            const size_t o = (size_t)(t + i) * (D_SZ / 2);
            kk[i] = __half22float2(kp[o]);
            vv[i] = __half22float2(vp[o]);
            rr[i] = __half22float2(rp[o]);
        }
#pragma unroll
        for (int i = 0; i < 8; i++) {
            const float ekx = __expf(kk[i].x);
            const float eky = __expf(kk[i].y);
            nx = fmaf(wx, nx, ekx * vv[i].x);
            ny = fmaf(wy, ny, eky * vv[i].y);
            dx = fmaf(wx, dx, ekx);
            dy = fmaf(wy, dy, eky);
            float2 o2;
            o2.x = rr[i].x * __fdividef(nx, dx + 1e-8f);
            o2.y = rr[i].y * __fdividef(ny, dy + 1e-8f);
            *(float2*)(op + (size_t)(t + i) * D_SZ) = o2;
        }
    }

    if (seg == 0) {
        float* out2 = out + (size_t)B_SZ * T_SZ * D_SZ;
        *(float2*)(out2 + c) =
            *(const float2*)(x + (size_t)b * T_SZ * D_SZ + (size_t)(T_SZ - 2) * D_SZ + d);
    }
}

// ---------------- launch --------------------------------------------------------
extern "C" void kernel_launch(void* const* d_in, const int* in_sizes, int n_in,
                              void* d_out, int out_size)
{
    const float* x  = (const float*)d_in[0];
    const float* Wk = (const float*)d_in[1];
    const float* Wv = (const float*)d_in[2];
    const float* Wr = (const float*)d_in[3];
    const float* td = (const float*)d_in[4];
    float* out = (float*)d_out;

    cudaFuncSetAttribute(gemm_kv_wr_kernel,
                         cudaFuncAttributeMaxDynamicSharedMemorySize, GEMM_SMEM);
    cudaFuncSetAttribute(gemm_r_p1_kernel,
                         cudaFuncAttributeMaxDynamicSharedMemorySize, GEMM_SMEM);

    convert_xkv_kernel<<<(unsigned)((CV1_TOTAL + 255) / 256), 256>>>(x, Wk, Wv);

    gemm_kv_wr_kernel<<<KV_MERGE_BLKS, 256, GEMM_SMEM>>>(Wr);      // k,v GEMM + Wr conv

    gemm_r_p1_kernel<<<MERGE_BLKS, 256, GEMM_SMEM>>>(td);          // r GEMM + p1

    const int p2_total = N_SEG * CH2;    // 262144 threads
    wkv_p2_kernel<<<p2_total / 256, 256>>>(td, x, out);
}